// round 1
// baseline (speedup 1.0000x reference)
#include <cuda_runtime.h>
#include <cuda_bf16.h>
#include <cstdint>

// ---------------------------------------------------------------------------
// PatchNCELoss: B=8192, D=128, T=0.07
// loss[b] = logsumexp_k(S[b,k]/T) - S[b,b]/T
//   S[b,k] = use_v[b] ? fv_n[b].v_n[k] : fi_n[b].vi_n[k]
//   use_v[b] = (fv_n[b].v_n[b] >= fi_n[b].vi_n[b])
// All rows L2-normalized -> dots <= 1 -> fixed-max logsumexp:
//   loss = 1/T + log( sum_k exp((S[b,k]-1)/T) ) - pos[b]/T
// ---------------------------------------------------------------------------

#define BN 8192
#define DD 128
#define KSPLIT 7
#define NCHUNKS 64              // 8192 / 128 key chunks
static __device__ float g_Asel[BN * DD];      // compacted, normalized A rows
static __device__ float g_Vn[BN * DD];        // normalized v
static __device__ float g_VIn[BN * DD];       // normalized i
static __device__ float g_posT[BN];           // pos/T per slot
static __device__ int   g_orig[BN];           // slot -> original row
static __device__ int   g_cnt[2];
static __device__ float g_partial[KSPLIT * BN];

#define INV_T    14.285714285714286f
#define SCALE_L2 20.609929155556620f   /* log2(e)/T */

typedef unsigned long long ull;

#define FMA2(d, a, b, c) \
    asm("fma.rn.f32x2 %0, %1, %2, %3;" : "=l"(d) : "l"(a), "l"(b), "l"(c))

__device__ __forceinline__ float ex2f(float x) {
    float r;
    asm("ex2.approx.f32 %0, %1;" : "=f"(r) : "f"(x));
    return r;
}

// ---------------------------------------------------------------------------
__global__ void init_kernel() {
    if (threadIdx.x == 0) { g_cnt[0] = 0; g_cnt[1] = 0; }
}

// ---------------------------------------------------------------------------
// One block (128 threads) per row: norms, diag dots, branch select, compaction.
__global__ void prep_kernel(const float* __restrict__ fv,
                            const float* __restrict__ fi,
                            const float* __restrict__ v,
                            const float* __restrict__ vi) {
    int b = blockIdx.x;
    int t = threadIdx.x;
    float xfv = fv[b * DD + t];
    float xfi = fi[b * DD + t];
    float xv  = v [b * DD + t];
    float xi  = vi[b * DD + t];

    float s[6];
    s[0] = xfv * xfv; s[1] = xfi * xfi; s[2] = xv * xv;
    s[3] = xi * xi;   s[4] = xfv * xv;  s[5] = xfi * xi;
#pragma unroll
    for (int off = 16; off; off >>= 1)
#pragma unroll
        for (int k = 0; k < 6; ++k)
            s[k] += __shfl_xor_sync(0xffffffffu, s[k], off);

    __shared__ float sh[4][6];
    __shared__ float bc[3];
    __shared__ int   bsl[2];
    int w = t >> 5, lane = t & 31;
    if (lane == 0)
#pragma unroll
        for (int k = 0; k < 6; ++k) sh[w][k] = s[k];
    __syncthreads();

    if (t == 0) {
        float tot[6];
#pragma unroll
        for (int k = 0; k < 6; ++k)
            tot[k] = sh[0][k] + sh[1][k] + sh[2][k] + sh[3][k];
        float inv_fv = 1.f / fmaxf(sqrtf(tot[0]), 1e-12f);
        float inv_fi = 1.f / fmaxf(sqrtf(tot[1]), 1e-12f);
        float inv_v  = 1.f / fmaxf(sqrtf(tot[2]), 1e-12f);
        float inv_i  = 1.f / fmaxf(sqrtf(tot[3]), 1e-12f);
        float pos_v = tot[4] * inv_fv * inv_v;
        float pos_i = tot[5] * inv_fi * inv_i;
        bool use_v = (pos_v >= pos_i);
        int slot = use_v ? atomicAdd(&g_cnt[0], 1)
                         : (BN - 1 - atomicAdd(&g_cnt[1], 1));
        g_orig[slot] = b;
        g_posT[slot] = (use_v ? pos_v : pos_i) * INV_T;
        bc[0] = inv_v; bc[1] = inv_i; bc[2] = use_v ? inv_fv : inv_fi;
        bsl[0] = slot; bsl[1] = use_v ? 1 : 0;
    }
    __syncthreads();

    g_Vn [b * DD + t] = xv * bc[0];
    g_VIn[b * DD + t] = xi * bc[1];
    g_Asel[bsl[0] * DD + t] = (bsl[1] ? xfv : xfi) * bc[2];
}

// ---------------------------------------------------------------------------
// GEMM + row sum-of-exp. CTA = 128 rows x (its key chunks). 256 threads,
// 8x8 register tile, f32x2 FMAs paired over k.
// smem layout (floats): Asp[64][128] as float2 pairs over k, Ksp same, red[128][16]
__global__ __launch_bounds__(256, 1) void gemm_lse_kernel() {
    extern __shared__ float smf[];
    float* Asp = smf;                 // 16384 floats
    float* Ksp = smf + 16384;         // 16384 floats
    float* red = smf + 32768;         // 2048 floats

    int tid  = threadIdx.x;
    int rt   = blockIdx.x;
    int ks   = blockIdx.y;
    int row0 = rt * 128;
    int c0   = g_cnt[0];

    // Load A tile once: Asp is float2[kpair=64][m=128]
    {
        int m  = tid >> 1;
        int kh = (tid & 1) * 64;
        const float4* src = (const float4*)(g_Asel + (row0 + m) * DD + kh);
        float2* dst = (float2*)Asp;
#pragma unroll
        for (int q = 0; q < 16; ++q) {
            float4 vv = src[q];
            int kp = (kh + q * 4) >> 1;
            dst[kp * 128 + m]       = make_float2(vv.x, vv.y);
            dst[(kp + 1) * 128 + m] = make_float2(vv.z, vv.w);
        }
    }

    bool has0 = row0 < c0;
    bool has1 = row0 + 128 > c0;
    int tx = tid & 15, ty = tid >> 4;

    for (int g = 0; g < 2; ++g) {
        if (g == 0 && !has0) continue;
        if (g == 1 && !has1) continue;
        const float* Kmat = g ? g_VIn : g_Vn;

        float rsum[8];
#pragma unroll
        for (int i = 0; i < 8; ++i) rsum[i] = 0.f;

        for (int ch = ks; ch < NCHUNKS; ch += KSPLIT) {
            __syncthreads();  // previous chunk's readers done
            {
                int n  = tid >> 1;
                int kh = (tid & 1) * 64;
                const float4* src = (const float4*)(Kmat + (ch * 128 + n) * DD + kh);
                float2* dst = (float2*)Ksp;
#pragma unroll
                for (int q = 0; q < 16; ++q) {
                    float4 vv = src[q];
                    int kp = (kh + q * 4) >> 1;
                    dst[kp * 128 + n]       = make_float2(vv.x, vv.y);
                    dst[(kp + 1) * 128 + n] = make_float2(vv.z, vv.w);
                }
            }
            __syncthreads();

            ull acc[8][8];
#pragma unroll
            for (int i = 0; i < 8; ++i)
#pragma unroll
                for (int j = 0; j < 8; ++j) acc[i][j] = 0ull;

            const ull* A2 = (const ull*)Asp + ty;
            const ull* K2 = (const ull*)Ksp + tx;
#pragma unroll 4
            for (int p = 0; p < 64; ++p) {
                ull a2[8], b2[8];
#pragma unroll
                for (int i = 0; i < 8; ++i) a2[i] = A2[p * 128 + 16 * i];
#pragma unroll
                for (int j = 0; j < 8; ++j) b2[j] = K2[p * 128 + 16 * j];
#pragma unroll
                for (int i = 0; i < 8; ++i)
#pragma unroll
                    for (int j = 0; j < 8; ++j)
                        FMA2(acc[i][j], a2[i], b2[j], acc[i][j]);
            }

            // epilogue: sum halves, exp, accumulate row sums (fixed order)
#pragma unroll
            for (int i = 0; i < 8; ++i) {
                float rs = 0.f;
#pragma unroll
                for (int j = 0; j < 8; ++j) {
                    float lo, hi;
                    asm("mov.b64 {%0, %1}, %2;" : "=f"(lo), "=f"(hi) : "l"(acc[i][j]));
                    float c = lo + hi;
                    rs += ex2f((c - 1.0f) * SCALE_L2);
                }
                rsum[i] += rs;
            }
        }

        // reduce across the 16 tx lanes per row (deterministic order)
        __syncthreads();
#pragma unroll
        for (int i = 0; i < 8; ++i) red[(ty + 16 * i) * 16 + tx] = rsum[i];
        __syncthreads();
        if (tid < 128) {
            int m  = tid;
            int mg = row0 + m;
            bool valid = (g == 0) ? (mg < c0) : (mg >= c0);
            if (valid) {
                float sacc = 0.f;
#pragma unroll
                for (int x = 0; x < 16; ++x) sacc += red[m * 16 + x];
                g_partial[ks * BN + mg] = sacc;
            }
        }
        __syncthreads();
    }
}

// ---------------------------------------------------------------------------
__global__ void finalize_kernel(float* __restrict__ out) {
    int s = blockIdx.x * 256 + threadIdx.x;
    if (s < BN) {
        float sum = 0.f;
#pragma unroll
        for (int k = 0; k < KSPLIT; ++k) sum += g_partial[k * BN + s];
        out[g_orig[s]] = INV_T + logf(sum) - g_posT[s];
    }
}

// ---------------------------------------------------------------------------
extern "C" void kernel_launch(void* const* d_in, const int* in_sizes, int n_in,
                              void* d_out, int out_size) {
    (void)in_sizes; (void)n_in; (void)out_size;
    const float* fv = (const float*)d_in[0];
    const float* fi = (const float*)d_in[1];
    const float* v  = (const float*)d_in[2];
    const float* vi = (const float*)d_in[3];
    float* out = (float*)d_out;

    cudaFuncSetAttribute(gemm_lse_kernel,
                         cudaFuncAttributeMaxDynamicSharedMemorySize, 139264);

    init_kernel<<<1, 32>>>();
    prep_kernel<<<BN, 128>>>(fv, fi, v, vi);
    gemm_lse_kernel<<<dim3(64, KSPLIT), 256, 139264>>>();
    finalize_kernel<<<BN / 256, 256>>>(out);
}

// round 3
// speedup vs baseline: 4.2072x; 4.2072x over previous
#include <cuda_runtime.h>
#include <cstdint>

// ---------------------------------------------------------------------------
// PatchNCELoss B=8192 D=128 T=0.07 via mma.sync tf32 (HMMA).
// loss[b] = 1/T + log(sum_k exp((S[b,k]-1)/T)) - pos[b]/T
// ---------------------------------------------------------------------------

#define BN 8192
#define DD 128
#define KS 2
#define NC 32                 // 128-key chunks per CTA (8192/128/KS)
#define GRID_X 65
#define STRIDE 132            // padded smem row stride (floats)

#define INV_T    14.285714285714286f
#define SCALE_L2 20.609929155556620f   /* log2(e)/T */

static __device__ float g_Asel[BN * DD];
static __device__ float g_Vn[BN * DD];
static __device__ float g_VIn[BN * DD];
static __device__ float g_posT[BN];
static __device__ int   g_orig[BN];
static __device__ int   g_cnt[2];
static __device__ float g_partial[KS * BN];

// smem: A [128][132] | B0 [128][132] | B1 [128][132]
#define SM_TILE   (128 * STRIDE)
#define SMEM_TOT  (3 * SM_TILE * 4)

// ---------------------------------------------------------------------------
__device__ __forceinline__ float ex2f(float x) {
    float r; asm("ex2.approx.f32 %0,%1;" : "=f"(r) : "f"(x)); return r;
}
__device__ __forceinline__ float tf32r(float x) {
    float r; asm("cvt.rna.tf32.f32 %0,%1;" : "=f"(r) : "f"(x)); return r;
}
__device__ __forceinline__ uint32_t s2u(const void* p) {
    uint32_t a;
    asm("{ .reg .u64 t; cvta.to.shared.u64 t, %1; cvt.u32.u64 %0, t; }"
        : "=r"(a) : "l"(p));
    return a;
}
#define CPA16(dst, src) \
    asm volatile("cp.async.cg.shared.global [%0], [%1], 16;" :: "r"(dst), "l"(src))
#define CP_COMMIT() asm volatile("cp.async.commit_group;" ::: "memory")
#define CP_WAIT1()  asm volatile("cp.async.wait_group 1;" ::: "memory")
#define CP_WAIT0()  asm volatile("cp.async.wait_group 0;" ::: "memory")

__device__ __forceinline__ void mma_tf32(float* c, uint32_t a0, uint32_t a1,
                                         uint32_t a2, uint32_t a3,
                                         uint32_t b0, uint32_t b1) {
    asm volatile(
        "mma.sync.aligned.m16n8k8.row.col.f32.tf32.tf32.f32 "
        "{%0,%1,%2,%3}, {%4,%5,%6,%7}, {%8,%9}, {%0,%1,%2,%3};"
        : "+f"(c[0]), "+f"(c[1]), "+f"(c[2]), "+f"(c[3])
        : "r"(a0), "r"(a1), "r"(a2), "r"(a3), "r"(b0), "r"(b1));
}

// ---------------------------------------------------------------------------
__global__ void init_kernel() {
    if (threadIdx.x == 0) { g_cnt[0] = 0; g_cnt[1] = 0; }
}

// one block (128 thr) per row: norms, diag dots, branch select, compaction.
__global__ void prep_kernel(const float* __restrict__ fv,
                            const float* __restrict__ fi,
                            const float* __restrict__ v,
                            const float* __restrict__ vi) {
    int b = blockIdx.x;
    int t = threadIdx.x;
    float xfv = fv[b * DD + t];
    float xfi = fi[b * DD + t];
    float xv  = v [b * DD + t];
    float xi  = vi[b * DD + t];

    float s[6];
    s[0] = xfv * xfv; s[1] = xfi * xfi; s[2] = xv * xv;
    s[3] = xi * xi;   s[4] = xfv * xv;  s[5] = xfi * xi;
#pragma unroll
    for (int off = 16; off; off >>= 1)
#pragma unroll
        for (int k = 0; k < 6; ++k)
            s[k] += __shfl_xor_sync(0xffffffffu, s[k], off);

    __shared__ float sh[4][6];
    __shared__ float bc[3];
    __shared__ int   bsl[2];
    int w = t >> 5, lane = t & 31;
    if (lane == 0)
#pragma unroll
        for (int k = 0; k < 6; ++k) sh[w][k] = s[k];
    __syncthreads();

    if (t == 0) {
        float tot[6];
#pragma unroll
        for (int k = 0; k < 6; ++k)
            tot[k] = sh[0][k] + sh[1][k] + sh[2][k] + sh[3][k];
        float inv_fv = 1.f / fmaxf(sqrtf(tot[0]), 1e-12f);
        float inv_fi = 1.f / fmaxf(sqrtf(tot[1]), 1e-12f);
        float inv_v  = 1.f / fmaxf(sqrtf(tot[2]), 1e-12f);
        float inv_i  = 1.f / fmaxf(sqrtf(tot[3]), 1e-12f);
        float pos_v = tot[4] * inv_fv * inv_v;
        float pos_i = tot[5] * inv_fi * inv_i;
        bool use_v = (pos_v >= pos_i);
        int slot = use_v ? atomicAdd(&g_cnt[0], 1)
                         : (BN - 1 - atomicAdd(&g_cnt[1], 1));
        g_orig[slot] = b;
        g_posT[slot] = (use_v ? pos_v : pos_i) * INV_T;
        bc[0] = inv_v; bc[1] = inv_i; bc[2] = use_v ? inv_fv : inv_fi;
        bsl[0] = slot; bsl[1] = use_v ? 1 : 0;
    }
    __syncthreads();

    g_Vn [b * DD + t] = tf32r(xv * bc[0]);
    g_VIn[b * DD + t] = tf32r(xi * bc[1]);
    g_Asel[bsl[0] * DD + t] = tf32r((bsl[1] ? xfv : xfi) * bc[2]);
}

// ---------------------------------------------------------------------------
__device__ __forceinline__ void load_b_async(uint32_t smB,
                                             const float* __restrict__ src,
                                             int tid) {
#pragma unroll
    for (int q = 0; q < 16; ++q) {
        int i = tid + q * 256;
        int row = i >> 5, c4 = i & 31;
        CPA16(smB + (uint32_t)(row * STRIDE + c4 * 4) * 4u,
              src + row * DD + c4 * 4);
    }
}

__global__ __launch_bounds__(256, 1) void gemm_lse_kernel() {
    extern __shared__ float sm[];
    float* A_s = sm;
    __shared__ float red[128][4];

    const int tid  = threadIdx.x;
    const int lane = tid & 31;
    const int wid  = tid >> 5;
    const int wm = wid >> 2;      // 0..1 : 64-row block
    const int wn = wid & 3;       // 0..3 : 32-key block
    const int aq = lane >> 2;     // 0..7
    const int ar = lane & 3;      // 0..3

    const int c0 = g_cnt[0];
    int t0 = c0 >> 7; if (t0 > 63) t0 = 63;
    const int bx = blockIdx.x, ks = blockIdx.y;
    int grp, row0;
    if (bx <= t0) { grp = 0; row0 = bx * 128; }
    else          { grp = 1; row0 = (bx - 1) * 128; }
    const float* __restrict__ Kmat = grp ? g_VIn : g_Vn;

    const uint32_t smB0 = s2u(sm + SM_TILE);
    const uint32_t smB1 = s2u(sm + 2 * SM_TILE);

    // A tile 128x128 -> smem (padded stride)
    const float* __restrict__ Asrc = g_Asel + (size_t)row0 * DD;
#pragma unroll
    for (int q = 0; q < 16; ++q) {
        int i = tid + q * 256;
        int row = i >> 5, c4 = i & 31;
        float4 vv = __ldg((const float4*)(Asrc + row * DD + c4 * 4));
        *(float4*)(A_s + row * STRIDE + c4 * 4) = vv;
    }

    // prologue: B chunk 0
    load_b_async(smB0, Kmat + (size_t)ks * 128 * DD, tid);
    CP_COMMIT();

    const float* Abase = A_s + (wm * 64 + aq) * STRIDE + ar;
    float rsum[8];
#pragma unroll
    for (int i = 0; i < 8; ++i) rsum[i] = 0.f;

    for (int ci = 0; ci < NC; ++ci) {
        if (ci + 1 < NC) {
            int ch = ks + (ci + 1) * KS;
            load_b_async((ci + 1) & 1 ? smB1 : smB0,
                         Kmat + (size_t)ch * 128 * DD, tid);
            CP_COMMIT();
            CP_WAIT1();
        } else {
            CP_WAIT0();
        }
        __syncthreads();

        const float* Bbuf = sm + SM_TILE * (1 + (ci & 1));
        const float* Bbase = Bbuf + (wn * 32 + aq) * STRIDE + ar;

        float c[4][4][4];
#pragma unroll
        for (int mi = 0; mi < 4; ++mi)
#pragma unroll
            for (int ni = 0; ni < 4; ++ni)
#pragma unroll
                for (int x = 0; x < 4; ++x) c[mi][ni][x] = 0.f;

#pragma unroll
        for (int kk = 0; kk < 16; ++kk) {
            const int k0 = kk * 8;
            uint32_t a[4][4], b[4][2];
#pragma unroll
            for (int mi = 0; mi < 4; ++mi) {
                const float* p = Abase + mi * 16 * STRIDE + k0;
                a[mi][0] = __float_as_uint(p[0]);
                a[mi][1] = __float_as_uint(p[8 * STRIDE]);
                a[mi][2] = __float_as_uint(p[4]);
                a[mi][3] = __float_as_uint(p[8 * STRIDE + 4]);
            }
#pragma unroll
            for (int ni = 0; ni < 4; ++ni) {
                const float* p = Bbase + ni * 8 * STRIDE + k0;
                b[ni][0] = __float_as_uint(p[0]);
                b[ni][1] = __float_as_uint(p[4]);
            }
#pragma unroll
            for (int mi = 0; mi < 4; ++mi)
#pragma unroll
                for (int ni = 0; ni < 4; ++ni)
                    mma_tf32(c[mi][ni], a[mi][0], a[mi][1], a[mi][2], a[mi][3],
                             b[ni][0], b[ni][1]);
        }

        // epilogue: exp((S-1)/T) accumulated per row (fixed order)
#pragma unroll
        for (int mi = 0; mi < 4; ++mi) {
            float s0 = 0.f, s1 = 0.f;
#pragma unroll
            for (int ni = 0; ni < 4; ++ni) {
                s0 += ex2f(fmaf(c[mi][ni][0], SCALE_L2, -SCALE_L2));
                s0 += ex2f(fmaf(c[mi][ni][1], SCALE_L2, -SCALE_L2));
                s1 += ex2f(fmaf(c[mi][ni][2], SCALE_L2, -SCALE_L2));
                s1 += ex2f(fmaf(c[mi][ni][3], SCALE_L2, -SCALE_L2));
            }
            rsum[mi * 2]     += s0;
            rsum[mi * 2 + 1] += s1;
        }
        __syncthreads();
    }

    // reduce across the 4 col-lanes (ar) of each row
#pragma unroll
    for (int mi = 0; mi < 4; ++mi)
#pragma unroll
        for (int h = 0; h < 2; ++h) {
            float val = rsum[mi * 2 + h];
            val += __shfl_xor_sync(0xffffffffu, val, 1);
            val += __shfl_xor_sync(0xffffffffu, val, 2);
            if (ar == 0)
                red[wm * 64 + mi * 16 + h * 8 + aq][wn] = val;
        }
    __syncthreads();

    if (tid < 128) {
        int slot = row0 + tid;
        bool valid = (grp == 0) ? (slot < c0) : (slot >= c0);
        if (valid) {
            float sum = red[tid][0] + red[tid][1] + red[tid][2] + red[tid][3];
            g_partial[ks * BN + slot] = sum;
        }
    }
}

// ---------------------------------------------------------------------------
__global__ void finalize_kernel(float* __restrict__ out) {
    int s = blockIdx.x * 256 + threadIdx.x;
    if (s < BN) {
        float sum = g_partial[s] + g_partial[BN + s];
        out[g_orig[s]] = INV_T + logf(sum) - g_posT[s];
    }
}

// ---------------------------------------------------------------------------
extern "C" void kernel_launch(void* const* d_in, const int* in_sizes, int n_in,
                              void* d_out, int out_size) {
    (void)in_sizes; (void)n_in; (void)out_size;
    const float* fv = (const float*)d_in[0];
    const float* fi = (const float*)d_in[1];
    const float* v  = (const float*)d_in[2];
    const float* vi = (const float*)d_in[3];
    float* out = (float*)d_out;

    cudaFuncSetAttribute(gemm_lse_kernel,
                         cudaFuncAttributeMaxDynamicSharedMemorySize, SMEM_TOT);

    init_kernel<<<1, 32>>>();
    prep_kernel<<<BN, 128>>>(fv, fi, v, vi);
    gemm_lse_kernel<<<dim3(GRID_X, KS), 256, SMEM_TOT>>>();
    finalize_kernel<<<BN / 256, 256>>>(out);
}

// round 4
// speedup vs baseline: 7.5253x; 1.7887x over previous
#include <cuda_runtime.h>
#include <cuda_fp16.h>
#include <cstdint>

// ---------------------------------------------------------------------------
// PatchNCELoss B=8192 D=128 T=0.07 via mma.sync m16n8k16 fp16 (HMMA).
// loss[b] = 1/T + log(sum_k exp((S[b,k]-1)/T)) - pos[b]/T
// A/B stored in gmem pre-permuted to mma fragment order -> LDS.128/LDS.64.
// Compacted rows padded to 65*128 arena; 128 zero pad rows at group boundary.
// ---------------------------------------------------------------------------

#define BN  8192
#define BN2 8320              // 65 * 128
#define DD  128
#define KS  4                 // key splits
#define NC  16                // 128-key chunks per CTA (8192/128/KS)
#define GRID_X 65

#define INV_T    14.285714285714286f
#define SCALE_L2 20.609929155556620f   /* log2(e)/T */

static __device__ __half g_Ap[BN2 * DD];   // fragment-permuted A (by slot)
static __device__ __half g_Bv[BN * DD];    // fragment-permuted v_n keys
static __device__ __half g_Bi[BN * DD];    // fragment-permuted i_n keys
static __device__ float  g_posT[BN2];
static __device__ int    g_orig[BN2];
static __device__ int    g_cnt[2];
static __device__ float  g_partial[KS * BN2];

// smem: A 32KB | B0 32KB | B1 32KB
#define SMEM_TOT 98304

// ---------------------------------------------------------------------------
__device__ __forceinline__ float ex2f(float x) {
    float r; asm("ex2.approx.f32 %0,%1;" : "=f"(r) : "f"(x)); return r;
}
__device__ __forceinline__ uint32_t s2u(const void* p) {
    uint32_t a;
    asm("{ .reg .u64 t; cvta.to.shared.u64 t, %1; cvt.u32.u64 %0, t; }"
        : "=r"(a) : "l"(p));
    return a;
}
#define CPA16(dst, src) \
    asm volatile("cp.async.cg.shared.global [%0], [%1], 16;" :: "r"(dst), "l"(src))
#define CP_COMMIT() asm volatile("cp.async.commit_group;" ::: "memory")
#define CP_WAIT1()  asm volatile("cp.async.wait_group 1;" ::: "memory")
#define CP_WAIT0()  asm volatile("cp.async.wait_group 0;" ::: "memory")

#define LDS128(r, a) \
    asm volatile("ld.shared.v4.b32 {%0,%1,%2,%3}, [%4];" \
        : "=r"((r)[0]), "=r"((r)[1]), "=r"((r)[2]), "=r"((r)[3]) : "r"(a))
#define LDS64(r, a) \
    asm volatile("ld.shared.v2.b32 {%0,%1}, [%2];" \
        : "=r"((r)[0]), "=r"((r)[1]) : "r"(a))

__device__ __forceinline__ void mma16816(float* c, const uint32_t* a,
                                         const uint32_t* b) {
    asm volatile(
        "mma.sync.aligned.m16n8k16.row.col.f32.f16.f16.f32 "
        "{%0,%1,%2,%3}, {%4,%5,%6,%7}, {%8,%9}, {%0,%1,%2,%3};"
        : "+f"(c[0]), "+f"(c[1]), "+f"(c[2]), "+f"(c[3])
        : "r"(a[0]), "r"(a[1]), "r"(a[2]), "r"(a[3]), "r"(b[0]), "r"(b[1]));
}

// fragment-permuted half index helpers
__device__ __forceinline__ int a_perm_idx(int s, int t) {
    int mb = s >> 4, q = s & 15, g = q & 7, hi = q >> 3;
    int kk = t >> 4, tc = t & 15, kh = tc >> 3, t4 = (tc >> 1) & 3, h = tc & 1;
    int lane = g * 4 + t4, r = hi + 2 * kh;
    return (((mb * 8 + kk) * 32 + lane) << 3) + r * 2 + h;
}
__device__ __forceinline__ int b_perm_idx(int b, int t) {
    int nb = b >> 3, g = b & 7;
    int kk = t >> 4, tc = t & 15, kh = tc >> 3, t4 = (tc >> 1) & 3, h = tc & 1;
    int lane = g * 4 + t4;
    return (((nb * 8 + kk) * 32 + lane) << 2) + kh * 2 + h;
}

// ---------------------------------------------------------------------------
__global__ void init_kernel() {
    if (threadIdx.x == 0) { g_cnt[0] = 0; g_cnt[1] = 0; }
}

// one block (128 thr) per row: norms, diag dots, branch select, compaction,
// fp16 conversion + fragment-order scatter.
__global__ void prep_kernel(const float* __restrict__ fv,
                            const float* __restrict__ fi,
                            const float* __restrict__ v,
                            const float* __restrict__ vi) {
    int b = blockIdx.x;
    int t = threadIdx.x;
    float xfv = fv[b * DD + t];
    float xfi = fi[b * DD + t];
    float xv  = v [b * DD + t];
    float xi  = vi[b * DD + t];

    float s[6];
    s[0] = xfv * xfv; s[1] = xfi * xfi; s[2] = xv * xv;
    s[3] = xi * xi;   s[4] = xfv * xv;  s[5] = xfi * xi;
#pragma unroll
    for (int off = 16; off; off >>= 1)
#pragma unroll
        for (int k = 0; k < 6; ++k)
            s[k] += __shfl_xor_sync(0xffffffffu, s[k], off);

    __shared__ float sh[4][6];
    __shared__ float bc[3];
    __shared__ int   bsl[2];
    int w = t >> 5, lane = t & 31;
    if (lane == 0)
#pragma unroll
        for (int k = 0; k < 6; ++k) sh[w][k] = s[k];
    __syncthreads();

    if (t == 0) {
        float tot[6];
#pragma unroll
        for (int k = 0; k < 6; ++k)
            tot[k] = sh[0][k] + sh[1][k] + sh[2][k] + sh[3][k];
        float inv_fv = 1.f / fmaxf(sqrtf(tot[0]), 1e-12f);
        float inv_fi = 1.f / fmaxf(sqrtf(tot[1]), 1e-12f);
        float inv_v  = 1.f / fmaxf(sqrtf(tot[2]), 1e-12f);
        float inv_i  = 1.f / fmaxf(sqrtf(tot[3]), 1e-12f);
        float pos_v = tot[4] * inv_fv * inv_v;
        float pos_i = tot[5] * inv_fi * inv_i;
        bool use_v = (pos_v >= pos_i);
        int slot = use_v ? atomicAdd(&g_cnt[0], 1)
                         : (BN2 - 1 - atomicAdd(&g_cnt[1], 1));
        g_orig[slot] = b;
        g_posT[slot] = (use_v ? pos_v : pos_i) * INV_T;
        bc[0] = inv_v; bc[1] = inv_i; bc[2] = use_v ? inv_fv : inv_fi;
        bsl[0] = slot; bsl[1] = use_v ? 1 : 0;
    }
    __syncthreads();

    g_Bv[b_perm_idx(b, t)] = __float2half_rn(xv * bc[0]);
    g_Bi[b_perm_idx(b, t)] = __float2half_rn(xi * bc[1]);
    g_Ap[a_perm_idx(bsl[0], t)] =
        __float2half_rn((bsl[1] ? xfv : xfi) * bc[2]);
}

// zero the 128 pad rows [c0, c0+128) and mark them invalid
__global__ void zero_pad_kernel() {
    int row = g_cnt[0] + blockIdx.x;
    int t = threadIdx.x;
    g_Ap[a_perm_idx(row, t)] = __float2half_rn(0.f);
    if (t == 0) g_orig[row] = -1;
}

// ---------------------------------------------------------------------------
__global__ __launch_bounds__(256, 2) void gemm_lse_kernel() {
    extern __shared__ __align__(16) unsigned char sm[];
    __shared__ float red[128][4];

    const uint32_t smA  = s2u(sm);
    const uint32_t smB0 = smA + 32768u;
    const uint32_t smB1 = smA + 65536u;

    const int tid  = threadIdx.x;
    const int lane = tid & 31;
    const int wid  = tid >> 5;
    const int wm = wid >> 2;          // 0..1  (64-row block)
    const int wn = wid & 3;           // 0..3  (32-key block)

    const int c0 = g_cnt[0];
    const int bx = blockIdx.x, ks = blockIdx.y;
    const int grp = (bx > (c0 >> 7)) ? 1 : 0;
    const int row0 = bx << 7;
    const char* __restrict__ Kb = (const char*)(grp ? g_Bi : g_Bv);

    // A tile (128 rows, fragment order, 32KB contiguous)
    {
        const char* Asrc = (const char*)g_Ap + (size_t)row0 * 256;
#pragma unroll
        for (int q = 0; q < 8; ++q) {
            int i = (tid + q * 256) * 16;
            CPA16(smA + (uint32_t)i, Asrc + i);
        }
    }
    // B chunk 0
    {
        const char* Bsrc = Kb + (size_t)ks * 32768;
#pragma unroll
        for (int q = 0; q < 8; ++q) {
            int i = (tid + q * 256) * 16;
            CPA16(smB0 + (uint32_t)i, Bsrc + i);
        }
    }
    CP_COMMIT();

    float rsum[8];
#pragma unroll
    for (int i = 0; i < 8; ++i) rsum[i] = 0.f;

    const uint32_t aoff = (uint32_t)(wm * 16384 + lane * 16);
    const uint32_t boff = (uint32_t)(wn * 8192 + lane * 8);

    for (int ci = 0; ci < NC; ++ci) {
        if (ci + 1 < NC) {
            const char* Bsrc = Kb + (size_t)(ks + (ci + 1) * KS) * 32768;
            uint32_t dst = ((ci + 1) & 1) ? smB1 : smB0;
#pragma unroll
            for (int q = 0; q < 8; ++q) {
                int i = (tid + q * 256) * 16;
                CPA16(dst + (uint32_t)i, Bsrc + i);
            }
            CP_COMMIT();
            CP_WAIT1();
        } else {
            CP_WAIT0();
        }
        __syncthreads();

        const uint32_t sB = ((ci & 1) ? smB1 : smB0) + boff;
        const uint32_t sA = smA + aoff;

        float c[4][4][4];
#pragma unroll
        for (int mi = 0; mi < 4; ++mi)
#pragma unroll
            for (int ni = 0; ni < 4; ++ni)
#pragma unroll
                for (int x = 0; x < 4; ++x) c[mi][ni][x] = 0.f;

#pragma unroll
        for (int kk = 0; kk < 8; ++kk) {
            uint32_t a[4][4], b[4][2];
#pragma unroll
            for (int mi = 0; mi < 4; ++mi)
                LDS128(a[mi], sA + (uint32_t)(mi * 4096 + kk * 512));
#pragma unroll
            for (int ni = 0; ni < 4; ++ni)
                LDS64(b[ni], sB + (uint32_t)(ni * 2048 + kk * 256));
#pragma unroll
            for (int mi = 0; mi < 4; ++mi)
#pragma unroll
                for (int ni = 0; ni < 4; ++ni)
                    mma16816(c[mi][ni], a[mi], b[ni]);
        }

        // epilogue: exp((S-1)/T), fixed accumulation order
#pragma unroll
        for (int mi = 0; mi < 4; ++mi) {
            float s0 = 0.f, s1 = 0.f;
#pragma unroll
            for (int ni = 0; ni < 4; ++ni) {
                s0 += ex2f(fmaf(c[mi][ni][0], SCALE_L2, -SCALE_L2));
                s0 += ex2f(fmaf(c[mi][ni][1], SCALE_L2, -SCALE_L2));
                s1 += ex2f(fmaf(c[mi][ni][2], SCALE_L2, -SCALE_L2));
                s1 += ex2f(fmaf(c[mi][ni][3], SCALE_L2, -SCALE_L2));
            }
            rsum[mi * 2]     += s0;
            rsum[mi * 2 + 1] += s1;
        }
        __syncthreads();
    }

    // reduce across the 4 col-lanes of each row
#pragma unroll
    for (int mi = 0; mi < 4; ++mi)
#pragma unroll
        for (int h = 0; h < 2; ++h) {
            float val = rsum[mi * 2 + h];
            val += __shfl_xor_sync(0xffffffffu, val, 1);
            val += __shfl_xor_sync(0xffffffffu, val, 2);
            if ((lane & 3) == 0)
                red[wm * 64 + mi * 16 + h * 8 + (lane >> 2)][wn] = val;
        }
    __syncthreads();

    if (tid < 128) {
        int slot = row0 + tid;
        float sum = red[tid][0] + red[tid][1] + red[tid][2] + red[tid][3];
        g_partial[ks * BN2 + slot] = sum;
    }
}

// ---------------------------------------------------------------------------
__global__ void finalize_kernel(float* __restrict__ out) {
    int s = blockIdx.x * 256 + threadIdx.x;
    if (s < BN2) {
        int o = g_orig[s];
        if (o >= 0) {
            float sum = g_partial[s] + g_partial[BN2 + s] +
                        g_partial[2 * BN2 + s] + g_partial[3 * BN2 + s];
            out[o] = INV_T + logf(sum) - g_posT[s];
        }
    }
}

// ---------------------------------------------------------------------------
extern "C" void kernel_launch(void* const* d_in, const int* in_sizes, int n_in,
                              void* d_out, int out_size) {
    (void)in_sizes; (void)n_in; (void)out_size;
    const float* fv = (const float*)d_in[0];
    const float* fi = (const float*)d_in[1];
    const float* v  = (const float*)d_in[2];
    const float* vi = (const float*)d_in[3];
    float* out = (float*)d_out;

    cudaFuncSetAttribute(gemm_lse_kernel,
                         cudaFuncAttributeMaxDynamicSharedMemorySize, SMEM_TOT);

    init_kernel<<<1, 32>>>();
    prep_kernel<<<BN, 128>>>(fv, fi, v, vi);
    zero_pad_kernel<<<128, 128>>>();
    gemm_lse_kernel<<<dim3(GRID_X, KS), 256, SMEM_TOT>>>();
    finalize_kernel<<<(BN2 + 255) / 256, 256>>>(out);
}

// round 5
// speedup vs baseline: 7.7481x; 1.0296x over previous
#include <cuda_runtime.h>
#include <cuda_fp16.h>
#include <cstdint>

// ---------------------------------------------------------------------------
// PatchNCELoss B=8192 D=128 T=0.07 via mma.sync m16n8k16 fp16 (HMMA).
// loss[b] = 1/T + log(sum_k exp((S[b,k]-1)/T)) - pos[b]/T
// A pre-scaled by log2(e)/T; accumulators init to -log2(e)/T so epilogue is
// pure ex2 + add. Epilogue of chunk ci-1 interleaved into MMA loop of chunk
// ci via double-buffered accumulator banks (occupancy 1, 130 CTAs).
// ---------------------------------------------------------------------------

#define BN  8192
#define BN2 8320              // 65 * 128
#define DD  128
#define KS  2                 // key splits
#define NC  32                // 128-key chunks per CTA (8192/128/KS)
#define GRID_X 65

#define INV_T    14.285714285714286f
#define SCALE_L2 20.609929155556620f   /* log2(e)/T */

static __device__ __half g_Ap[BN2 * DD];   // fragment-permuted A * SCALE_L2
static __device__ __half g_Bv[BN * DD];    // fragment-permuted v_n keys
static __device__ __half g_Bi[BN * DD];    // fragment-permuted i_n keys
static __device__ float  g_posT[BN2];
static __device__ int    g_orig[BN2];
static __device__ int    g_cnt[2];
static __device__ float  g_partial[KS * BN2];

// smem: A 32KB | B0 32KB | B1 32KB
#define SMEM_TOT 98304

// ---------------------------------------------------------------------------
__device__ __forceinline__ float ex2f(float x) {
    float r; asm("ex2.approx.f32 %0,%1;" : "=f"(r) : "f"(x)); return r;
}
__device__ __forceinline__ uint32_t s2u(const void* p) {
    uint32_t a;
    asm("{ .reg .u64 t; cvta.to.shared.u64 t, %1; cvt.u32.u64 %0, t; }"
        : "=r"(a) : "l"(p));
    return a;
}
#define CPA16(dst, src) \
    asm volatile("cp.async.cg.shared.global [%0], [%1], 16;" :: "r"(dst), "l"(src))
#define CP_COMMIT() asm volatile("cp.async.commit_group;" ::: "memory")
#define CP_WAIT1()  asm volatile("cp.async.wait_group 1;" ::: "memory")

#define LDS128(r, a) \
    asm volatile("ld.shared.v4.b32 {%0,%1,%2,%3}, [%4];" \
        : "=r"((r)[0]), "=r"((r)[1]), "=r"((r)[2]), "=r"((r)[3]) : "r"(a))
#define LDS64(r, a) \
    asm volatile("ld.shared.v2.b32 {%0,%1}, [%2];" \
        : "=r"((r)[0]), "=r"((r)[1]) : "r"(a))

__device__ __forceinline__ void mma16816(float* c, const uint32_t* a,
                                         const uint32_t* b) {
    asm volatile(
        "mma.sync.aligned.m16n8k16.row.col.f32.f16.f16.f32 "
        "{%0,%1,%2,%3}, {%4,%5,%6,%7}, {%8,%9}, {%0,%1,%2,%3};"
        : "+f"(c[0]), "+f"(c[1]), "+f"(c[2]), "+f"(c[3])
        : "r"(a[0]), "r"(a[1]), "r"(a[2]), "r"(a[3]), "r"(b[0]), "r"(b[1]));
}

// fragment-permuted half index helpers
__device__ __forceinline__ int a_perm_idx(int s, int t) {
    int mb = s >> 4, q = s & 15, g = q & 7, hi = q >> 3;
    int kk = t >> 4, tc = t & 15, kh = tc >> 3, t4 = (tc >> 1) & 3, h = tc & 1;
    int lane = g * 4 + t4, r = hi + 2 * kh;
    return (((mb * 8 + kk) * 32 + lane) << 3) + r * 2 + h;
}
__device__ __forceinline__ int b_perm_idx(int b, int t) {
    int nb = b >> 3, g = b & 7;
    int kk = t >> 4, tc = t & 15, kh = tc >> 3, t4 = (tc >> 1) & 3, h = tc & 1;
    int lane = g * 4 + t4;
    return (((nb * 8 + kk) * 32 + lane) << 2) + kh * 2 + h;
}

// ---------------------------------------------------------------------------
__global__ void init_kernel() {
    if (threadIdx.x == 0) { g_cnt[0] = 0; g_cnt[1] = 0; }
}

__global__ void prep_kernel(const float* __restrict__ fv,
                            const float* __restrict__ fi,
                            const float* __restrict__ v,
                            const float* __restrict__ vi) {
    int b = blockIdx.x;
    int t = threadIdx.x;
    float xfv = fv[b * DD + t];
    float xfi = fi[b * DD + t];
    float xv  = v [b * DD + t];
    float xi  = vi[b * DD + t];

    float s[6];
    s[0] = xfv * xfv; s[1] = xfi * xfi; s[2] = xv * xv;
    s[3] = xi * xi;   s[4] = xfv * xv;  s[5] = xfi * xi;
#pragma unroll
    for (int off = 16; off; off >>= 1)
#pragma unroll
        for (int k = 0; k < 6; ++k)
            s[k] += __shfl_xor_sync(0xffffffffu, s[k], off);

    __shared__ float sh[4][6];
    __shared__ float bc[3];
    __shared__ int   bsl[2];
    int w = t >> 5, lane = t & 31;
    if (lane == 0)
#pragma unroll
        for (int k = 0; k < 6; ++k) sh[w][k] = s[k];
    __syncthreads();

    if (t == 0) {
        float tot[6];
#pragma unroll
        for (int k = 0; k < 6; ++k)
            tot[k] = sh[0][k] + sh[1][k] + sh[2][k] + sh[3][k];
        float inv_fv = 1.f / fmaxf(sqrtf(tot[0]), 1e-12f);
        float inv_fi = 1.f / fmaxf(sqrtf(tot[1]), 1e-12f);
        float inv_v  = 1.f / fmaxf(sqrtf(tot[2]), 1e-12f);
        float inv_i  = 1.f / fmaxf(sqrtf(tot[3]), 1e-12f);
        float pos_v = tot[4] * inv_fv * inv_v;
        float pos_i = tot[5] * inv_fi * inv_i;
        bool use_v = (pos_v >= pos_i);
        int slot = use_v ? atomicAdd(&g_cnt[0], 1)
                         : (BN2 - 1 - atomicAdd(&g_cnt[1], 1));
        g_orig[slot] = b;
        g_posT[slot] = (use_v ? pos_v : pos_i) * INV_T;
        bc[0] = inv_v; bc[1] = inv_i; bc[2] = use_v ? inv_fv : inv_fi;
        bsl[0] = slot; bsl[1] = use_v ? 1 : 0;
    }
    __syncthreads();

    g_Bv[b_perm_idx(b, t)] = __float2half_rn(xv * bc[0]);
    g_Bi[b_perm_idx(b, t)] = __float2half_rn(xi * bc[1]);
    g_Ap[a_perm_idx(bsl[0], t)] =
        __float2half_rn((bsl[1] ? xfv : xfi) * bc[2] * SCALE_L2);
}

__global__ void zero_pad_kernel() {
    int row = g_cnt[0] + blockIdx.x;
    int t = threadIdx.x;
    g_Ap[a_perm_idx(row, t)] = __float2half_rn(0.f);
    if (t == 0) g_orig[row] = -1;
}

// ---------------------------------------------------------------------------
// chunk body: init+MMA into bank c, epilogue (if EPI) reads bank e, interleaved
template <bool EPI>
__device__ __forceinline__ void mma_chunk(uint32_t sA, uint32_t sB,
                                          float (&c)[4][4][4],
                                          float (&e)[4][4][4],
                                          float (&rsum)[8]) {
#pragma unroll
    for (int mi = 0; mi < 4; ++mi)
#pragma unroll
        for (int ni = 0; ni < 4; ++ni)
#pragma unroll
            for (int x = 0; x < 4; ++x) c[mi][ni][x] = -SCALE_L2;

#pragma unroll
    for (int kk = 0; kk < 8; ++kk) {
        uint32_t a[4][4], b[4][2];
#pragma unroll
        for (int mi = 0; mi < 4; ++mi)
            LDS128(a[mi], sA + (uint32_t)(mi * 4096 + kk * 512));
#pragma unroll
        for (int ni = 0; ni < 4; ++ni)
            LDS64(b[ni], sB + (uint32_t)(ni * 2048 + kk * 256));
#pragma unroll
        for (int mi = 0; mi < 4; ++mi)
#pragma unroll
            for (int ni = 0; ni < 4; ++ni)
                mma16816(c[mi][ni], a[mi], b[ni]);

        if (EPI) {
            // 2 of the 16 epilogue tiles per kk step (prev chunk's bank)
#pragma unroll
            for (int u = 0; u < 2; ++u) {
                int tI = kk * 2 + u;
                int mi = tI >> 2, ni = tI & 3;
                rsum[mi * 2]     += ex2f(e[mi][ni][0]) + ex2f(e[mi][ni][1]);
                rsum[mi * 2 + 1] += ex2f(e[mi][ni][2]) + ex2f(e[mi][ni][3]);
            }
        }
    }
}

__device__ __forceinline__ void epi_only(float (&e)[4][4][4],
                                         float (&rsum)[8]) {
#pragma unroll
    for (int mi = 0; mi < 4; ++mi)
#pragma unroll
        for (int ni = 0; ni < 4; ++ni) {
            rsum[mi * 2]     += ex2f(e[mi][ni][0]) + ex2f(e[mi][ni][1]);
            rsum[mi * 2 + 1] += ex2f(e[mi][ni][2]) + ex2f(e[mi][ni][3]);
        }
}

__global__ __launch_bounds__(256, 1) void gemm_lse_kernel() {
    extern __shared__ __align__(16) unsigned char sm[];
    __shared__ float red[128][4];

    const uint32_t smA  = s2u(sm);
    const uint32_t smB0 = smA + 32768u;
    const uint32_t smB1 = smA + 65536u;

    const int tid  = threadIdx.x;
    const int lane = tid & 31;
    const int wid  = tid >> 5;
    const int wm = wid >> 2;
    const int wn = wid & 3;

    const int c0 = g_cnt[0];
    const int bx = blockIdx.x, ks = blockIdx.y;
    const int grp = (bx > (c0 >> 7)) ? 1 : 0;
    const int row0 = bx << 7;
    const char* __restrict__ Kb = (const char*)(grp ? g_Bi : g_Bv);

    // group 0: A + B0 ; group 1: B1
    {
        const char* Asrc = (const char*)g_Ap + (size_t)row0 * 256;
#pragma unroll
        for (int q = 0; q < 8; ++q) {
            int i = (tid + q * 256) * 16;
            CPA16(smA + (uint32_t)i, Asrc + i);
        }
        const char* Bsrc = Kb + (size_t)ks * 32768;
#pragma unroll
        for (int q = 0; q < 8; ++q) {
            int i = (tid + q * 256) * 16;
            CPA16(smB0 + (uint32_t)i, Bsrc + i);
        }
        CP_COMMIT();
        Bsrc = Kb + (size_t)(ks + KS) * 32768;
#pragma unroll
        for (int q = 0; q < 8; ++q) {
            int i = (tid + q * 256) * 16;
            CPA16(smB1 + (uint32_t)i, Bsrc + i);
        }
        CP_COMMIT();
    }
    CP_WAIT1();
    __syncthreads();

    float cb0[4][4][4], cb1[4][4][4];
    float rsum[8];
#pragma unroll
    for (int i = 0; i < 8; ++i) rsum[i] = 0.f;

    const uint32_t aoff = smA + (uint32_t)(wm * 16384 + lane * 16);
    const uint32_t boff0 = smB0 + (uint32_t)(wn * 8192 + lane * 8);
    const uint32_t boff1 = smB1 + (uint32_t)(wn * 8192 + lane * 8);

    // end-of-chunk: prefetch B(ci+2) into buf(ci&1), ensure B(ci+1) ready
#define ENDCHUNK(ci, dstB)                                                    \
    do {                                                                      \
        __syncthreads();                                                      \
        if ((ci) + 2 < NC) {                                                  \
            const char* Bs = Kb + (size_t)(ks + ((ci) + 2) * KS) * 32768;     \
            _Pragma("unroll")                                                 \
            for (int q = 0; q < 8; ++q) {                                     \
                int i = (tid + q * 256) * 16;                                 \
                CPA16((dstB) + (uint32_t)i, Bs + i);                          \
            }                                                                 \
        }                                                                     \
        CP_COMMIT();                                                          \
        CP_WAIT1();                                                           \
        __syncthreads();                                                      \
    } while (0)

    // chunk 0 (no epilogue)
    mma_chunk<false>(aoff, boff0, cb0, cb1, rsum);
    ENDCHUNK(0, smB0);

#pragma unroll 1
    for (int p = 0; p < (NC - 2) / 2; ++p) {
        int ci = 1 + 2 * p;
        mma_chunk<true>(aoff, boff1, cb1, cb0, rsum);   // chunk ci, epi ci-1
        ENDCHUNK(ci, smB1);
        mma_chunk<true>(aoff, boff0, cb0, cb1, rsum);   // chunk ci+1, epi ci
        ENDCHUNK(ci + 1, smB0);
    }
    // chunk NC-1 (odd -> buf1/bank1), epi NC-2
    mma_chunk<true>(aoff, boff1, cb1, cb0, rsum);
    epi_only(cb1, rsum);
#undef ENDCHUNK

    // reduce across the 4 col-lanes of each row
#pragma unroll
    for (int mi = 0; mi < 4; ++mi)
#pragma unroll
        for (int h = 0; h < 2; ++h) {
            float val = rsum[mi * 2 + h];
            val += __shfl_xor_sync(0xffffffffu, val, 1);
            val += __shfl_xor_sync(0xffffffffu, val, 2);
            if ((lane & 3) == 0)
                red[wm * 64 + mi * 16 + h * 8 + (lane >> 2)][wn] = val;
        }
    __syncthreads();

    if (tid < 128) {
        int slot = row0 + tid;
        float sum = red[tid][0] + red[tid][1] + red[tid][2] + red[tid][3];
        g_partial[ks * BN2 + slot] = sum;
    }
}

// ---------------------------------------------------------------------------
__global__ void finalize_kernel(float* __restrict__ out) {
    int s = blockIdx.x * 256 + threadIdx.x;
    if (s < BN2) {
        int o = g_orig[s];
        if (o >= 0) {
            float sum = g_partial[s] + g_partial[BN2 + s];
            out[o] = INV_T + logf(sum) - g_posT[s];
        }
    }
}

// ---------------------------------------------------------------------------
extern "C" void kernel_launch(void* const* d_in, const int* in_sizes, int n_in,
                              void* d_out, int out_size) {
    (void)in_sizes; (void)n_in; (void)out_size;
    const float* fv = (const float*)d_in[0];
    const float* fi = (const float*)d_in[1];
    const float* v  = (const float*)d_in[2];
    const float* vi = (const float*)d_in[3];
    float* out = (float*)d_out;

    cudaFuncSetAttribute(gemm_lse_kernel,
                         cudaFuncAttributeMaxDynamicSharedMemorySize, SMEM_TOT);

    init_kernel<<<1, 32>>>();
    prep_kernel<<<BN, 128>>>(fv, fi, v, vi);
    zero_pad_kernel<<<128, 128>>>();
    gemm_lse_kernel<<<dim3(GRID_X, KS), 256, SMEM_TOT>>>();
    finalize_kernel<<<(BN2 + 255) / 256, 256>>>(out);
}